// round 12
// baseline (speedup 1.0000x reference)
#include <cuda_runtime.h>
#include <cuda_bf16.h>
#include <math.h>

#define Sn 256
#define Bn 128
#define En 256
#define Hn 512
#define Tn 18
#define G4n 2048

// ---------------- scratch (device globals; no cudaMalloc allowed) ----------------
__device__ __nv_bfloat16 d_xb[Sn * Bn * En];          // embedded input, bf16
__device__ __nv_bfloat16 d_xp_f[Sn * Bn * G4n];       // input projection fwd [t][b][g*512+j] bf16
__device__ __nv_bfloat16 d_xp_b[Sn * Bn * G4n];       // input projection bwd bf16
__device__ __nv_bfloat16 d_out0b[Sn * Bn * 2 * Hn];   // layer0 output bf16 [t][b][2H]
__device__ __nv_bfloat16 d_out1b[Sn * Bn * 2 * Hn];   // layer1 output bf16
__device__ float d_hfc[Sn * Bn * Hn];
__device__ float d_em[Sn * Bn * Tn];
__device__ __nv_bfloat16 d_hstb[2][2][Bn * Hn];       // h state bf16 [dir][parity][b*H+j]
__device__ float d_num[Bn];
__device__ float d_den[Bn];
__device__ int d_bflags[2][2][32];                    // [dir][batch-half][jblk] step flags
// bf16 weight copies (input projections + fc)
__device__ __nv_bfloat16 d_wb_l0f[G4n * En];
__device__ __nv_bfloat16 d_wb_l0b[G4n * En];
__device__ __nv_bfloat16 d_wb_l1f[G4n * 2 * Hn];
__device__ __nv_bfloat16 d_wb_l1b[G4n * 2 * Hn];
__device__ __nv_bfloat16 d_wb_fc[Hn * 2 * Hn];

template<int N> __device__ __forceinline__ void cpwait() {
    asm volatile("cp.async.wait_group %0;" :: "n"(N));
}
__device__ __forceinline__ void cpcommit() {
    asm volatile("cp.async.commit_group;");
}
__device__ __forceinline__ void cpasync16(unsigned dst, const void* src) {
    asm volatile("cp.async.cg.shared.global [%0], [%1], 16;" :: "r"(dst), "l"(src));
}

// ---------------- fp32 -> bf16 convert ----------------
__global__ void f2bf_kernel(const float* __restrict__ src, __nv_bfloat16* __restrict__ dst, int n4)
{
    int i = blockIdx.x * blockDim.x + threadIdx.x;
    if (i >= n4) return;
    float4 v = ((const float4*)src)[i];
    __nv_bfloat162 h0 = __floats2bfloat162_rn(v.x, v.y);
    __nv_bfloat162 h1 = __floats2bfloat162_rn(v.z, v.w);
    ((__nv_bfloat162*)dst)[i * 2]     = h0;
    ((__nv_bfloat162*)dst)[i * 2 + 1] = h1;
}

// ---------------- embedding lookup (padding_idx=0 -> zeros), bf16 out ----------------
__global__ void embed_kernel(const int* __restrict__ ids, const float* __restrict__ emb)
{
    int n = blockIdx.x;          // n = s*B + b
    int s = n >> 7;
    int b = n & 127;
    int id = ids[b * Sn + s];
    float4 v;
    if (id == 0) v = make_float4(0.f, 0.f, 0.f, 0.f);
    else         v = ((const float4*)(emb + (size_t)id * En))[threadIdx.x];
    __nv_bfloat162 h0 = __floats2bfloat162_rn(v.x, v.y);
    __nv_bfloat162 h1 = __floats2bfloat162_rn(v.z, v.w);
    __nv_bfloat162* dst = (__nv_bfloat162*)(d_xb + (size_t)n * En);
    dst[threadIdx.x * 2]     = h0;
    dst[threadIdx.x * 2 + 1] = h1;
}

// ---------------- bf16 TC GEMM (NT), 2-stage cp.async pipeline (R7-proven) -------
__global__ __launch_bounds__(256) void gemm_bf16(
    const __nv_bfloat16* __restrict__ A, const __nv_bfloat16* __restrict__ W,
    const float* __restrict__ bias, float* __restrict__ Cf,
    __nv_bfloat16* __restrict__ Cb,
    int N, int K, int relu, int outbf)
{
    __shared__ __nv_bfloat16 As[2][128 * 40];
    __shared__ __nv_bfloat16 Bs[2][128 * 40];

    int tid = threadIdx.x;
    int lane = tid & 31, wid = tid >> 5;
    int wm = wid >> 2, wn = wid & 3;
    int m0 = blockIdx.y << 7, n0 = blockIdx.x << 7;

    unsigned as_u32 = (unsigned)__cvta_generic_to_shared(&As[0][0]);
    unsigned bs_u32 = (unsigned)__cvta_generic_to_shared(&Bs[0][0]);
    unsigned a_base = as_u32 + ((wm * 64 + (lane & 15)) * 40 + ((lane >> 4) * 8)) * 2;
    unsigned b_base = bs_u32 + ((wn * 32 + (lane & 7)) * 40 + (((lane >> 3) & 1) * 8)) * 2;
    const unsigned STB = 128 * 40 * 2;

    int r0 = (tid * 2) >> 2,     c0 = ((tid * 2) & 3) * 8;
    int r1 = (tid * 2 + 1) >> 2, c1 = ((tid * 2 + 1) & 3) * 8;

    float acc[4][4][4];
#pragma unroll
    for (int i = 0; i < 4; i++)
#pragma unroll
        for (int j = 0; j < 4; j++)
#pragma unroll
            for (int r = 0; r < 4; r++) acc[i][j][r] = 0.f;

    cpasync16(as_u32 + (r0 * 40 + c0) * 2, &A[(size_t)(m0 + r0) * K + c0]);
    cpasync16(as_u32 + (r1 * 40 + c1) * 2, &A[(size_t)(m0 + r1) * K + c1]);
    cpasync16(bs_u32 + (r0 * 40 + c0) * 2, &W[(size_t)(n0 + r0) * K + c0]);
    cpasync16(bs_u32 + (r1 * 40 + c1) * 2, &W[(size_t)(n0 + r1) * K + c1]);
    cpcommit();

    int st = 0;
    for (int k0 = 0; k0 < K; k0 += 32) {
        bool more = (k0 + 32) < K;
        if (more) {
            unsigned so = (st ^ 1) * STB;
            cpasync16(as_u32 + so + (r0 * 40 + c0) * 2, &A[(size_t)(m0 + r0) * K + k0 + 32 + c0]);
            cpasync16(as_u32 + so + (r1 * 40 + c1) * 2, &A[(size_t)(m0 + r1) * K + k0 + 32 + c1]);
            cpasync16(bs_u32 + so + (r0 * 40 + c0) * 2, &W[(size_t)(n0 + r0) * K + k0 + 32 + c0]);
            cpasync16(bs_u32 + so + (r1 * 40 + c1) * 2, &W[(size_t)(n0 + r1) * K + k0 + 32 + c1]);
            cpcommit();
            cpwait<1>();
        } else {
            cpwait<0>();
        }
        __syncthreads();

        unsigned so = st * STB;
#pragma unroll
        for (int kk = 0; kk < 2; kk++) {
            unsigned af[4][4], bf[4][2];
#pragma unroll
            for (int i = 0; i < 4; i++) {
                unsigned addr = a_base + so + i * 1280 + kk * 32;
                asm volatile("ldmatrix.sync.aligned.m8n8.x4.shared.b16 {%0,%1,%2,%3}, [%4];"
                    : "=r"(af[i][0]), "=r"(af[i][1]), "=r"(af[i][2]), "=r"(af[i][3])
                    : "r"(addr));
            }
#pragma unroll
            for (int j = 0; j < 4; j++) {
                unsigned addr = b_base + so + j * 640 + kk * 32;
                asm volatile("ldmatrix.sync.aligned.m8n8.x2.shared.b16 {%0,%1}, [%2];"
                    : "=r"(bf[j][0]), "=r"(bf[j][1]) : "r"(addr));
            }
#pragma unroll
            for (int i = 0; i < 4; i++)
#pragma unroll
                for (int j = 0; j < 4; j++) {
                    asm volatile(
                        "mma.sync.aligned.m16n8k16.row.col.f32.bf16.bf16.f32 "
                        "{%0,%1,%2,%3}, {%4,%5,%6,%7}, {%8,%9}, {%0,%1,%2,%3};"
                        : "+f"(acc[i][j][0]), "+f"(acc[i][j][1]),
                          "+f"(acc[i][j][2]), "+f"(acc[i][j][3])
                        : "r"(af[i][0]), "r"(af[i][1]), "r"(af[i][2]), "r"(af[i][3]),
                          "r"(bf[j][0]), "r"(bf[j][1]));
                }
        }
        __syncthreads();
        st ^= 1;
    }

#pragma unroll
    for (int i = 0; i < 4; i++) {
        int mb = m0 + wm * 64 + i * 16 + (lane >> 2);
#pragma unroll
        for (int j = 0; j < 4; j++) {
            int nb = n0 + wn * 32 + j * 8 + (lane & 3) * 2;
            float bx = bias[nb], by = bias[nb + 1];
            float2 v0 = make_float2(acc[i][j][0] + bx, acc[i][j][1] + by);
            float2 v1 = make_float2(acc[i][j][2] + bx, acc[i][j][3] + by);
            if (relu) {
                v0.x = fmaxf(v0.x, 0.f); v0.y = fmaxf(v0.y, 0.f);
                v1.x = fmaxf(v1.x, 0.f); v1.y = fmaxf(v1.y, 0.f);
            }
            if (outbf) {
                *(__nv_bfloat162*)&Cb[(size_t)mb * N + nb]       = __floats2bfloat162_rn(v0.x, v0.y);
                *(__nv_bfloat162*)&Cb[(size_t)(mb + 8) * N + nb] = __floats2bfloat162_rn(v1.x, v1.y);
            } else {
                *(float2*)&Cf[(size_t)mb * N + nb]       = v0;
                *(float2*)&Cf[(size_t)(mb + 8) * N + nb] = v1;
            }
        }
    }
}

// ---------------- persistent BiLSTM layer, tensor-core recurrence, M=64xN=64 -----
// grid = 128 blocks: dir(2) x batch-half(2) x jblk(32). 256 threads, 2x4 warp grid.
// Block computes gates for 64 batch rows x 16 j-cols (64 n = 16j x 4 gates).
// h tile per block = 64 rows x 512 = 64KB (half the old traffic). Sync groups of
// 32 blocks (same dir+half) via per-block flag array (no atomic serialization).
__global__ __launch_bounds__(256) void persist_lstm_tc(
    const __nv_bfloat16* __restrict__ xpf, const __nv_bfloat16* __restrict__ xpb,
    const float* __restrict__ whhf, const float* __restrict__ whhb,
    __nv_bfloat16* __restrict__ out)
{
    extern __shared__ __nv_bfloat16 smb[];
    __nv_bfloat16* hs = smb;                       // [64][520] bf16 (66560 B)
    __nv_bfloat16* ws = smb + 64 * 520;            // [64][520] bf16 (66560 B)
    float* gsm = (float*)(smb + 128 * 520);        // [64][68] f32 (17408 B)

    int bid = blockIdx.x;
    int dir  = bid >> 6;
    int half = (bid >> 5) & 1;
    int jblk = bid & 31;
    int j0 = jblk * 16;
    const __nv_bfloat16* xp = dir ? xpb : xpf;
    const float* whh = dir ? whhb : whhf;
    int* flg = &d_bflags[dir][half][0];

    int tid = threadIdx.x;
    int lane = tid & 31, wid = tid >> 5;
    int wm = wid >> 2, wn = wid & 3;               // 2x4 warp grid
    int jl = tid & 15, bg = tid >> 4;              // 16 j x 16 batch-groups
    int b0v = bg * 4;                               // local batch base (0..60)
    int j = j0 + jl;

    // load Whh slice -> bf16 smem: row n = jl*4+g  <->  whh row (g*512 + j0 + (n>>2))
#pragma unroll 4
    for (int it = 0; it < 128; it++) {
        int idx = it * 256 + tid;
        int n = idx >> 9, k = idx & 511;
        int grow = (n & 3) * Hn + j0 + (n >> 2);
        ws[n * 520 + k] = __float2bfloat16(whh[(size_t)grow * Hn + k]);
    }
    float c4[4] = {0.f, 0.f, 0.f, 0.f};
    __syncthreads();

    unsigned hs_u = (unsigned)__cvta_generic_to_shared(hs);
    unsigned ws_u = (unsigned)__cvta_generic_to_shared(ws);
    unsigned a_base = hs_u + ((wm * 32 + (lane & 15)) * 520 + (lane >> 4) * 8) * 2;
    unsigned b_base = ws_u + ((wn * 16 + (lane & 7)) * 520 + ((lane >> 3) & 1) * 8) * 2;

    for (int s = 0; s < Sn; s++) {
        int t = dir ? (Sn - 1 - s) : s;
        const __nv_bfloat16* hin = d_hstb[dir][s & 1] + half * 64 * Hn;
        __nv_bfloat16* hout = d_hstb[dir][(s & 1) ^ 1];

        // issue h loads: 8 chunks x 8KB (64 rows x 64 k-cols), one commit group each
#pragma unroll
        for (int ch = 0; ch < 8; ch++) {
#pragma unroll
            for (int it = 0; it < 2; it++) {
                int idx = it * 256 + tid;      // 0..511
                int b = idx >> 3;
                int cq = idx & 7;
                cpasync16(hs_u + (b * 520 + ch * 64 + cq * 8) * 2,
                          hin + (size_t)b * Hn + ch * 64 + cq * 8);
            }
            cpcommit();
        }

        // prefetch xp gate pre-activations (bf16, overlaps with cp.async)
        float xr[4][4];
#pragma unroll
        for (int bi = 0; bi < 4; bi++) {
            size_t xb = ((size_t)t * Bn + half * 64 + b0v + bi) * G4n;
#pragma unroll
            for (int g = 0; g < 4; g++)
                xr[bi][g] = __bfloat162float(xp[xb + g * Hn + j]);
        }

        float acc[2][2][4];
#pragma unroll
        for (int i = 0; i < 2; i++)
#pragma unroll
            for (int jt = 0; jt < 2; jt++)
#pragma unroll
                for (int r = 0; r < 4; r++) acc[i][jt][r] = 0.f;

        // consume chunks as they land
#pragma unroll
        for (int ch = 0; ch < 8; ch++) {
            if      (ch == 0) cpwait<7>();
            else if (ch == 1) cpwait<6>();
            else if (ch == 2) cpwait<5>();
            else if (ch == 3) cpwait<4>();
            else if (ch == 4) cpwait<3>();
            else if (ch == 5) cpwait<2>();
            else if (ch == 6) cpwait<1>();
            else              cpwait<0>();
            __syncthreads();
#pragma unroll
            for (int k2 = 0; k2 < 4; k2++) {
                int k = ch * 4 + k2;
                unsigned af[2][4], bfr[2][2];
#pragma unroll
                for (int i = 0; i < 2; i++) {
                    unsigned addr = a_base + i * (16 * 520 * 2) + k * 32;
                    asm volatile("ldmatrix.sync.aligned.m8n8.x4.shared.b16 {%0,%1,%2,%3}, [%4];"
                        : "=r"(af[i][0]), "=r"(af[i][1]), "=r"(af[i][2]), "=r"(af[i][3])
                        : "r"(addr));
                }
#pragma unroll
                for (int jt = 0; jt < 2; jt++) {
                    unsigned addr = b_base + jt * (8 * 520 * 2) + k * 32;
                    asm volatile("ldmatrix.sync.aligned.m8n8.x2.shared.b16 {%0,%1}, [%2];"
                        : "=r"(bfr[jt][0]), "=r"(bfr[jt][1]) : "r"(addr));
                }
#pragma unroll
                for (int i = 0; i < 2; i++)
#pragma unroll
                    for (int jt = 0; jt < 2; jt++) {
                        asm volatile(
                            "mma.sync.aligned.m16n8k16.row.col.f32.bf16.bf16.f32 "
                            "{%0,%1,%2,%3}, {%4,%5,%6,%7}, {%8,%9}, {%0,%1,%2,%3};"
                            : "+f"(acc[i][jt][0]), "+f"(acc[i][jt][1]),
                              "+f"(acc[i][jt][2]), "+f"(acc[i][jt][3])
                            : "r"(af[i][0]), "r"(af[i][1]), "r"(af[i][2]), "r"(af[i][3]),
                              "r"(bfr[jt][0]), "r"(bfr[jt][1]));
                    }
            }
        }

        // fragments -> gsm[n][m]  (n = output col, m = local batch row)
#pragma unroll
        for (int i = 0; i < 2; i++) {
            int m = wm * 32 + i * 16 + (lane >> 2);
#pragma unroll
            for (int jt = 0; jt < 2; jt++) {
                int n = wn * 16 + jt * 8 + (lane & 3) * 2;
                gsm[n * 68 + m]           = acc[i][jt][0];
                gsm[(n + 1) * 68 + m]     = acc[i][jt][1];
                gsm[n * 68 + m + 8]       = acc[i][jt][2];
                gsm[(n + 1) * 68 + m + 8] = acc[i][jt][3];
            }
        }
        __syncthreads();

        // epilogue: gates, activations, h/out stores
#pragma unroll
        for (int bi = 0; bi < 4; bi++) {
            int bl = b0v + bi;
            int b = half * 64 + bl;
            float gi = gsm[(jl * 4 + 0) * 68 + bl] + xr[bi][0];
            float gf = gsm[(jl * 4 + 1) * 68 + bl] + xr[bi][1];
            float gg = gsm[(jl * 4 + 2) * 68 + bl] + xr[bi][2];
            float go = gsm[(jl * 4 + 3) * 68 + bl] + xr[bi][3];
            float ig = 1.f / (1.f + expf(-gi));
            float fg = 1.f / (1.f + expf(-gf));
            float og = 1.f / (1.f + expf(-go));
            float cc = fg * c4[bi] + ig * tanhf(gg);
            float hh = og * tanhf(cc);
            c4[bi] = cc;
            __nv_bfloat16 hb = __float2bfloat16(hh);
            hout[b * Hn + j] = hb;
            out[((size_t)t * Bn + b) * (2 * Hn) + dir * Hn + j] = hb;
        }

        // flag-array barrier over the 32 producer blocks of this (dir, half)
        __syncthreads();
        if (tid == 0) {
            __threadfence();
            *(volatile int*)&flg[jblk] = s + 1;
        }
        if (tid < 32) {
            volatile int* vf = (volatile int*)flg;
            while (!__all_sync(0xffffffffu, vf[tid] > s)) { }
        }
        __syncthreads();
    }
}

// ---------------- emissions: em[row][t] = hfc[row] . cls_w[t] + cls_b[t] ----------
__global__ void emissions_kernel(const float* __restrict__ hfc,
                                 const float* __restrict__ cls_w,
                                 const float* __restrict__ cls_b)
{
    int warp = blockIdx.x * 8 + (threadIdx.x >> 5);
    int lane = threadIdx.x & 31;
    const float* hrow = hfc + (size_t)warp * Hn;
    float hv[16];
#pragma unroll
    for (int q = 0; q < 16; q++) hv[q] = hrow[lane + q * 32];
    for (int tt = 0; tt < Tn; tt++) {
        const float* wr = cls_w + tt * Hn;
        float s = 0.f;
#pragma unroll
        for (int q = 0; q < 16; q++) s += hv[q] * wr[lane + q * 32];
#pragma unroll
        for (int o = 16; o > 0; o >>= 1) s += __shfl_xor_sync(0xffffffffu, s, o);
        if (lane == 0) d_em[(size_t)warp * Tn + tt] = s + cls_b[tt];
    }
}

// ---------------- CRF gold-path score (numerator), parallel over s ----------------
__global__ void crf_num_kernel(const int* __restrict__ ids, const int* __restrict__ tags,
                               const float* __restrict__ trans,
                               const float* __restrict__ start_t, const float* __restrict__ end_t)
{
    int b = blockIdx.x;
    int lane = threadIdx.x;   // 32
    float score = 0.f;
    int cnt = 0;
    for (int s = lane; s < Sn; s += 32) {
        int tg = tags[b * Sn + s];
        bool m = ids[b * Sn + s] != 0;
        if (s == 0) {
            score += start_t[tg] + d_em[(size_t)b * Tn + tg];
            if (m) cnt++;
        } else if (m) {
            int pv = tags[b * Sn + s - 1];
            score += trans[pv * Tn + tg] + d_em[((size_t)s * Bn + b) * Tn + tg];
            cnt++;
        }
    }
#pragma unroll
    for (int o = 16; o > 0; o >>= 1) {
        score += __shfl_xor_sync(0xffffffffu, score, o);
        cnt   += __shfl_xor_sync(0xffffffffu, cnt, o);
    }
    if (lane == 0) {
        int se = cnt - 1; if (se < 0) se = 0;
        d_num[b] = score + end_t[tags[b * Sn + se]];
    }
}

// ---------------- CRF forward algorithm (denominator) ----------------
__global__ void crf_fwd_kernel(const int* __restrict__ ids,
                               const float* __restrict__ trans,
                               const float* __restrict__ start_t,
                               const float* __restrict__ end_t)
{
    int b = blockIdx.x;
    int j = threadIdx.x;
    __shared__ float alpha[Tn];
    __shared__ float tr[Tn * Tn];
    for (int idx = j; idx < Tn * Tn; idx += 32) tr[idx] = trans[idx];
    if (j < Tn) alpha[j] = start_t[j] + d_em[(size_t)b * Tn + j];
    __syncthreads();
    for (int s = 1; s < Sn; s++) {
        bool m = ids[b * Sn + s] != 0;
        float ns = 0.f;
        if (m && j < Tn) {
            float mx = -1e30f;
#pragma unroll
            for (int i = 0; i < Tn; i++) mx = fmaxf(mx, alpha[i] + tr[i * Tn + j]);
            float sum = 0.f;
#pragma unroll
            for (int i = 0; i < Tn; i++) sum += expf(alpha[i] + tr[i * Tn + j] - mx);
            ns = mx + logf(sum) + d_em[((size_t)s * Bn + b) * Tn + j];
        }
        __syncthreads();
        if (m && j < Tn) alpha[j] = ns;
        __syncthreads();
    }
    if (j == 0) {
        float mx = -1e30f;
        for (int i = 0; i < Tn; i++) mx = fmaxf(mx, alpha[i] + end_t[i]);
        float sum = 0.f;
        for (int i = 0; i < Tn; i++) sum += expf(alpha[i] + end_t[i] - mx);
        d_den[b] = mx + logf(sum);
    }
}

// ---------------- final: out = mean(num - den) ----------------
__global__ void final_kernel(float* __restrict__ out)
{
    int tid = threadIdx.x;
    __shared__ float sm[128];
    sm[tid] = d_num[tid] - d_den[tid];
    __syncthreads();
    for (int o = 64; o > 0; o >>= 1) {
        if (tid < o) sm[tid] += sm[tid + o];
        __syncthreads();
    }
    if (tid == 0) out[0] = sm[0] / 128.f;
}

// ---------------- launch ----------------
extern "C" void kernel_launch(void* const* d_in, const int* in_sizes, int n_in,
                              void* d_out, int out_size)
{
    (void)in_sizes; (void)n_in; (void)out_size;
    const int*   ids      = (const int*)d_in[0];
    const int*   tags     = (const int*)d_in[1];
    const float* emb      = (const float*)d_in[2];
    const float* w_ih_l0f = (const float*)d_in[3];
    const float* w_hh_l0f = (const float*)d_in[4];
    const float* b_l0f    = (const float*)d_in[5];
    const float* w_ih_l0b = (const float*)d_in[6];
    const float* w_hh_l0b = (const float*)d_in[7];
    const float* b_l0b    = (const float*)d_in[8];
    const float* w_ih_l1f = (const float*)d_in[9];
    const float* w_hh_l1f = (const float*)d_in[10];
    const float* b_l1f    = (const float*)d_in[11];
    const float* w_ih_l1b = (const float*)d_in[12];
    const float* w_hh_l1b = (const float*)d_in[13];
    const float* b_l1b    = (const float*)d_in[14];
    const float* fc_w     = (const float*)d_in[15];
    const float* fc_b     = (const float*)d_in[16];
    const float* cls_w    = (const float*)d_in[17];
    const float* cls_b    = (const float*)d_in[18];
    const float* trans    = (const float*)d_in[19];
    const float* start_t  = (const float*)d_in[20];
    const float* end_t    = (const float*)d_in[21];
    float* out = (float*)d_out;

    float *phfc;
    __nv_bfloat16 *pxbuf, *pxf, *pxb, *pout0b, *pout1b, *pw0f, *pw0b, *pw1f, *pw1b, *pwfc, *phstb;
    int* pbflags;
    cudaGetSymbolAddress((void**)&pxbuf, d_xb);
    cudaGetSymbolAddress((void**)&pxf,   d_xp_f);
    cudaGetSymbolAddress((void**)&pxb,   d_xp_b);
    cudaGetSymbolAddress((void**)&pout0b, d_out0b);
    cudaGetSymbolAddress((void**)&pout1b, d_out1b);
    cudaGetSymbolAddress((void**)&phfc,  d_hfc);
    cudaGetSymbolAddress((void**)&phstb, d_hstb);
    cudaGetSymbolAddress((void**)&pbflags, d_bflags);
    cudaGetSymbolAddress((void**)&pw0f,  d_wb_l0f);
    cudaGetSymbolAddress((void**)&pw0b,  d_wb_l0b);
    cudaGetSymbolAddress((void**)&pw1f,  d_wb_l1f);
    cudaGetSymbolAddress((void**)&pw1b,  d_wb_l1b);
    cudaGetSymbolAddress((void**)&pwfc,  d_wb_fc);

    const int SMEM_LSTM = 64 * 520 * 2 + 64 * 520 * 2 + 64 * 68 * 4;  // 150528 B
    cudaFuncSetAttribute(persist_lstm_tc, cudaFuncAttributeMaxDynamicSharedMemorySize, SMEM_LSTM);

    // weight converts for the big GEMMs
    f2bf_kernel<<<(G4n * En / 4 + 255) / 256, 256>>>(w_ih_l0f, pw0f, G4n * En / 4);
    f2bf_kernel<<<(G4n * En / 4 + 255) / 256, 256>>>(w_ih_l0b, pw0b, G4n * En / 4);
    f2bf_kernel<<<(G4n * 2 * Hn / 4 + 255) / 256, 256>>>(w_ih_l1f, pw1f, G4n * 2 * Hn / 4);
    f2bf_kernel<<<(G4n * 2 * Hn / 4 + 255) / 256, 256>>>(w_ih_l1b, pw1b, G4n * 2 * Hn / 4);
    f2bf_kernel<<<(Hn * 2 * Hn / 4 + 255) / 256, 256>>>(fc_w, pwfc, Hn * 2 * Hn / 4);

    embed_kernel<<<Sn * Bn, 64>>>(ids, emb);

    // layer 0 input projections (row-major xp [t][b][g*512+j], bf16 out)
    dim3 g0(G4n / 128, (Sn * Bn) / 128);
    gemm_bf16<<<g0, 256>>>(pxbuf, pw0f, b_l0f, nullptr, pxf, G4n, En, 0, 1);
    gemm_bf16<<<g0, 256>>>(pxbuf, pw0b, b_l0b, nullptr, pxb, G4n, En, 0, 1);

    cudaMemsetAsync(phstb, 0, sizeof(d_hstb), 0);
    cudaMemsetAsync(pbflags, 0, sizeof(d_bflags), 0);
    persist_lstm_tc<<<128, 256, SMEM_LSTM>>>(pxf, pxb, w_hh_l0f, w_hh_l0b, pout0b);

    // layer 1 input projections
    gemm_bf16<<<g0, 256>>>(pout0b, pw1f, b_l1f, nullptr, pxf, G4n, 2 * Hn, 0, 1);
    gemm_bf16<<<g0, 256>>>(pout0b, pw1b, b_l1b, nullptr, pxb, G4n, 2 * Hn, 0, 1);

    cudaMemsetAsync(phstb, 0, sizeof(d_hstb), 0);
    cudaMemsetAsync(pbflags, 0, sizeof(d_bflags), 0);
    persist_lstm_tc<<<128, 256, SMEM_LSTM>>>(pxf, pxb, w_hh_l1f, w_hh_l1b, pout1b);

    // fc + relu (fp32 out for emissions)
    dim3 gfc(Hn / 128, (Sn * Bn) / 128);
    gemm_bf16<<<gfc, 256>>>(pout1b, pwfc, fc_b, phfc, nullptr, Hn, 2 * Hn, 1, 0);

    emissions_kernel<<<(Sn * Bn) / 8, 256>>>(phfc, cls_w, cls_b);
    crf_num_kernel<<<Bn, 32>>>(ids, tags, trans, start_t, end_t);
    crf_fwd_kernel<<<Bn, 32>>>(ids, trans, start_t, end_t);
    final_kernel<<<1, Bn>>>(out);
}

// round 13
// speedup vs baseline: 1.0839x; 1.0839x over previous
#include <cuda_runtime.h>
#include <cuda_bf16.h>
#include <math.h>

#define Sn 256
#define Bn 128
#define En 256
#define Hn 512
#define Tn 18
#define G4n 2048

// ---------------- scratch (device globals; no cudaMalloc allowed) ----------------
__device__ __nv_bfloat16 d_xb[Sn * Bn * En];          // embedded input, bf16
__device__ float d_xp_f[Sn * Bn * G4n];               // input projection fwd [t][b][g*512+j]
__device__ float d_xp_b[Sn * Bn * G4n];               // input projection bwd
__device__ __nv_bfloat16 d_out0b[Sn * Bn * 2 * Hn];   // layer0 output bf16 [t][b][2H]
__device__ __nv_bfloat16 d_out1b[Sn * Bn * 2 * Hn];   // layer1 output bf16
__device__ float d_hfc[Sn * Bn * Hn];
__device__ float d_em[Sn * Bn * Tn];
__device__ __nv_bfloat16 d_hstb[2][2][Bn * Hn];       // h state bf16 [dir][parity][b*H+j]
__device__ float d_num[Bn];
__device__ float d_den[Bn];
__device__ unsigned g_cnt[2];
__device__ volatile unsigned g_gen[2];
// bf16 weight copies (input projections + fc)
__device__ __nv_bfloat16 d_wb_l0f[G4n * En];
__device__ __nv_bfloat16 d_wb_l0b[G4n * En];
__device__ __nv_bfloat16 d_wb_l1f[G4n * 2 * Hn];
__device__ __nv_bfloat16 d_wb_l1b[G4n * 2 * Hn];
__device__ __nv_bfloat16 d_wb_fc[Hn * 2 * Hn];

template<int N> __device__ __forceinline__ void cpwait() {
    asm volatile("cp.async.wait_group %0;" :: "n"(N));
}
__device__ __forceinline__ void cpcommit() {
    asm volatile("cp.async.commit_group;");
}
__device__ __forceinline__ void cpasync16(unsigned dst, const void* src) {
    asm volatile("cp.async.cg.shared.global [%0], [%1], 16;" :: "r"(dst), "l"(src));
}

// ---------------- fp32 -> bf16 convert ----------------
__global__ void f2bf_kernel(const float* __restrict__ src, __nv_bfloat16* __restrict__ dst, int n4)
{
    int i = blockIdx.x * blockDim.x + threadIdx.x;
    if (i >= n4) return;
    float4 v = ((const float4*)src)[i];
    __nv_bfloat162 h0 = __floats2bfloat162_rn(v.x, v.y);
    __nv_bfloat162 h1 = __floats2bfloat162_rn(v.z, v.w);
    ((__nv_bfloat162*)dst)[i * 2]     = h0;
    ((__nv_bfloat162*)dst)[i * 2 + 1] = h1;
}

// ---------------- embedding lookup (padding_idx=0 -> zeros), bf16 out ----------------
__global__ void embed_kernel(const int* __restrict__ ids, const float* __restrict__ emb)
{
    int n = blockIdx.x;          // n = s*B + b
    int s = n >> 7;
    int b = n & 127;
    int id = ids[b * Sn + s];
    float4 v;
    if (id == 0) v = make_float4(0.f, 0.f, 0.f, 0.f);
    else         v = ((const float4*)(emb + (size_t)id * En))[threadIdx.x];
    __nv_bfloat162 h0 = __floats2bfloat162_rn(v.x, v.y);
    __nv_bfloat162 h1 = __floats2bfloat162_rn(v.z, v.w);
    __nv_bfloat162* dst = (__nv_bfloat162*)(d_xb + (size_t)n * En);
    dst[threadIdx.x * 2]     = h0;
    dst[threadIdx.x * 2 + 1] = h1;
}

// ---------------- bf16 TC GEMM (NT), 2-stage cp.async pipeline, BK=64 ------------
// C[M,N] = A[M,K] * W[N,K]^T + bias. BM=128, BN=128, BK=64, 256 thr (8 warps 2x4).
// Dynamic smem: 2 stages x (A,B) x 128 x 72 bf16 = 73728 B. K % 64 == 0.
__global__ __launch_bounds__(256) void gemm_bf16(
    const __nv_bfloat16* __restrict__ A, const __nv_bfloat16* __restrict__ W,
    const float* __restrict__ bias, float* __restrict__ C,
    int N, int K, int relu)
{
    extern __shared__ __nv_bfloat16 gsmem[];
    __nv_bfloat16* As = gsmem;                 // [2][128*72]
    __nv_bfloat16* Bs = gsmem + 2 * 128 * 72;  // [2][128*72]

    int tid = threadIdx.x;
    int lane = tid & 31, wid = tid >> 5;
    int wm = wid >> 2, wn = wid & 3;
    int m0 = blockIdx.y << 7, n0 = blockIdx.x << 7;

    unsigned as_u32 = (unsigned)__cvta_generic_to_shared(As);
    unsigned bs_u32 = (unsigned)__cvta_generic_to_shared(Bs);
    unsigned a_base = as_u32 + ((wm * 64 + (lane & 15)) * 72 + ((lane >> 4) * 8)) * 2;
    unsigned b_base = bs_u32 + ((wn * 32 + (lane & 7)) * 72 + (((lane >> 3) & 1) * 8)) * 2;
    const unsigned STB = 128 * 72 * 2;   // stage stride bytes

    // per-thread load coords: 4 x 16B per matrix per stage (128 rows x 64 cols)
    int rr[4], cc[4];
#pragma unroll
    for (int i = 0; i < 4; i++) {
        int q = tid * 4 + i;
        rr[i] = q >> 3;
        cc[i] = (q & 7) * 8;
    }

    float acc[4][4][4];
#pragma unroll
    for (int i = 0; i < 4; i++)
#pragma unroll
        for (int j = 0; j < 4; j++)
#pragma unroll
            for (int r = 0; r < 4; r++) acc[i][j][r] = 0.f;

    // prologue: stage 0
#pragma unroll
    for (int i = 0; i < 4; i++) {
        cpasync16(as_u32 + (rr[i] * 72 + cc[i]) * 2, &A[(size_t)(m0 + rr[i]) * K + cc[i]]);
        cpasync16(bs_u32 + (rr[i] * 72 + cc[i]) * 2, &W[(size_t)(n0 + rr[i]) * K + cc[i]]);
    }
    cpcommit();

    int st = 0;
    for (int k0 = 0; k0 < K; k0 += 64) {
        bool more = (k0 + 64) < K;
        if (more) {
            unsigned so = (st ^ 1) * STB;
#pragma unroll
            for (int i = 0; i < 4; i++) {
                cpasync16(as_u32 + so + (rr[i] * 72 + cc[i]) * 2,
                          &A[(size_t)(m0 + rr[i]) * K + k0 + 64 + cc[i]]);
                cpasync16(bs_u32 + so + (rr[i] * 72 + cc[i]) * 2,
                          &W[(size_t)(n0 + rr[i]) * K + k0 + 64 + cc[i]]);
            }
            cpcommit();
            cpwait<1>();
        } else {
            cpwait<0>();
        }
        __syncthreads();

        unsigned so = st * STB;
#pragma unroll
        for (int kk = 0; kk < 4; kk++) {
            unsigned af[4][4], bf[4][2];
#pragma unroll
            for (int i = 0; i < 4; i++) {
                unsigned addr = a_base + so + i * (16 * 72 * 2) + kk * 32;
                asm volatile("ldmatrix.sync.aligned.m8n8.x4.shared.b16 {%0,%1,%2,%3}, [%4];"
                    : "=r"(af[i][0]), "=r"(af[i][1]), "=r"(af[i][2]), "=r"(af[i][3])
                    : "r"(addr));
            }
#pragma unroll
            for (int j = 0; j < 4; j++) {
                unsigned addr = b_base + so + j * (8 * 72 * 2) + kk * 32;
                asm volatile("ldmatrix.sync.aligned.m8n8.x2.shared.b16 {%0,%1}, [%2];"
                    : "=r"(bf[j][0]), "=r"(bf[j][1]) : "r"(addr));
            }
#pragma unroll
            for (int i = 0; i < 4; i++)
#pragma unroll
                for (int j = 0; j < 4; j++) {
                    asm volatile(
                        "mma.sync.aligned.m16n8k16.row.col.f32.bf16.bf16.f32 "
                        "{%0,%1,%2,%3}, {%4,%5,%6,%7}, {%8,%9}, {%0,%1,%2,%3};"
                        : "+f"(acc[i][j][0]), "+f"(acc[i][j][1]),
                          "+f"(acc[i][j][2]), "+f"(acc[i][j][3])
                        : "r"(af[i][0]), "r"(af[i][1]), "r"(af[i][2]), "r"(af[i][3]),
                          "r"(bf[j][0]), "r"(bf[j][1]));
                }
        }
        __syncthreads();
        st ^= 1;
    }

#pragma unroll
    for (int i = 0; i < 4; i++) {
        int mb = m0 + wm * 64 + i * 16 + (lane >> 2);
#pragma unroll
        for (int j = 0; j < 4; j++) {
            int nb = n0 + wn * 32 + j * 8 + (lane & 3) * 2;
            float bx = bias[nb], by = bias[nb + 1];
            float2 v0 = make_float2(acc[i][j][0] + bx, acc[i][j][1] + by);
            float2 v1 = make_float2(acc[i][j][2] + bx, acc[i][j][3] + by);
            if (relu) {
                v0.x = fmaxf(v0.x, 0.f); v0.y = fmaxf(v0.y, 0.f);
                v1.x = fmaxf(v1.x, 0.f); v1.y = fmaxf(v1.y, 0.f);
            }
            *(float2*)&C[(size_t)mb * N + nb]       = v0;
            *(float2*)&C[(size_t)(mb + 8) * N + nb] = v1;
        }
    }
}

// ---------------- persistent BiLSTM layer, tensor-core recurrence (R7-proven) ----
// grid = 128 blocks (64 per dir), 256 threads (8 warps, 4x2 warp grid).
// Per step: h load (8 cp.async chunks) overlapped with chunked MMA.
__global__ __launch_bounds__(256) void persist_lstm_tc(
    const float* __restrict__ xpf, const float* __restrict__ xpb,
    const float* __restrict__ whhf, const float* __restrict__ whhb,
    __nv_bfloat16* __restrict__ out)
{
    extern __shared__ __nv_bfloat16 smb[];
    __nv_bfloat16* hs = smb;                       // [128][520] bf16 (133120 B)
    __nv_bfloat16* ws = smb + 128 * 520;           // [32][520]  bf16 (33280 B)
    float* gsm = (float*)(smb + 128 * 520 + 32 * 520);  // [32][132] f32 (16896 B)

    int bid = blockIdx.x;
    int dir = bid >> 6;
    int j0 = (bid & 63) * 8;
    const float* xp  = dir ? xpb : xpf;
    const float* whh = dir ? whhb : whhf;

    int tid = threadIdx.x;
    int lane = tid & 31, wid = tid >> 5;
    int wm = wid >> 1, wn = wid & 1;               // 4x2 warp grid
    int jl = tid & 7, bg = tid >> 3;
    int b0v = bg * 4;
    int j = j0 + jl;

    // load Whh slice -> bf16 smem: row n = jl*4+g  <->  whh row (g*512 + j0 + jl)
#pragma unroll 4
    for (int it = 0; it < 64; it++) {
        int idx = it * 256 + tid;
        int n = idx >> 9, k = idx & 511;
        int grow = (n & 3) * Hn + j0 + (n >> 2);
        ws[n * 520 + k] = __float2bfloat16(whh[(size_t)grow * Hn + k]);
    }
    float c4[4] = {0.f, 0.f, 0.f, 0.f};
    __syncthreads();

    unsigned hs_u = (unsigned)__cvta_generic_to_shared(hs);
    unsigned ws_u = (unsigned)__cvta_generic_to_shared(ws);
    unsigned a_base = hs_u + ((wm * 32 + (lane & 15)) * 520 + (lane >> 4) * 8) * 2;
    unsigned b_base = ws_u + ((wn * 16 + (lane & 7)) * 520 + ((lane >> 3) & 1) * 8) * 2;

    for (int s = 0; s < Sn; s++) {
        int t = dir ? (Sn - 1 - s) : s;
        const __nv_bfloat16* hin = d_hstb[dir][s & 1];
        __nv_bfloat16* hout = d_hstb[dir][(s & 1) ^ 1];

        // issue h loads: 8 chunks x 16KB (64 k-cols each), one commit group each
#pragma unroll
        for (int ch = 0; ch < 8; ch++) {
#pragma unroll
            for (int it = 0; it < 4; it++) {
                int idx = it * 256 + tid;      // 0..1023
                int b = idx >> 3;
                int cq = idx & 7;
                cpasync16(hs_u + (b * 520 + ch * 64 + cq * 8) * 2,
                          hin + (size_t)b * Hn + ch * 64 + cq * 8);
            }
            cpcommit();
        }

        // prefetch xp gate pre-activations (overlaps with cp.async)
        float xr[4][4];
#pragma unroll
        for (int bi = 0; bi < 4; bi++) {
            size_t xb = ((size_t)t * Bn + b0v + bi) * G4n;
#pragma unroll
            for (int g = 0; g < 4; g++)
                xr[bi][g] = xp[xb + g * Hn + j];
        }

        float acc[2][2][4];
#pragma unroll
        for (int i = 0; i < 2; i++)
#pragma unroll
            for (int jt = 0; jt < 2; jt++)
#pragma unroll
                for (int r = 0; r < 4; r++) acc[i][jt][r] = 0.f;

        // consume chunks as they land
#pragma unroll
        for (int ch = 0; ch < 8; ch++) {
            if      (ch == 0) cpwait<7>();
            else if (ch == 1) cpwait<6>();
            else if (ch == 2) cpwait<5>();
            else if (ch == 3) cpwait<4>();
            else if (ch == 4) cpwait<3>();
            else if (ch == 5) cpwait<2>();
            else if (ch == 6) cpwait<1>();
            else              cpwait<0>();
            __syncthreads();
#pragma unroll
            for (int k2 = 0; k2 < 4; k2++) {
                int k = ch * 4 + k2;
                unsigned af[2][4], bfr[2][2];
#pragma unroll
                for (int i = 0; i < 2; i++) {
                    unsigned addr = a_base + i * (16 * 520 * 2) + k * 32;
                    asm volatile("ldmatrix.sync.aligned.m8n8.x4.shared.b16 {%0,%1,%2,%3}, [%4];"
                        : "=r"(af[i][0]), "=r"(af[i][1]), "=r"(af[i][2]), "=r"(af[i][3])
                        : "r"(addr));
                }
#pragma unroll
                for (int jt = 0; jt < 2; jt++) {
                    unsigned addr = b_base + jt * (8 * 520 * 2) + k * 32;
                    asm volatile("ldmatrix.sync.aligned.m8n8.x2.shared.b16 {%0,%1}, [%2];"
                        : "=r"(bfr[jt][0]), "=r"(bfr[jt][1]) : "r"(addr));
                }
#pragma unroll
                for (int i = 0; i < 2; i++)
#pragma unroll
                    for (int jt = 0; jt < 2; jt++) {
                        asm volatile(
                            "mma.sync.aligned.m16n8k16.row.col.f32.bf16.bf16.f32 "
                            "{%0,%1,%2,%3}, {%4,%5,%6,%7}, {%8,%9}, {%0,%1,%2,%3};"
                            : "+f"(acc[i][jt][0]), "+f"(acc[i][jt][1]),
                              "+f"(acc[i][jt][2]), "+f"(acc[i][jt][3])
                            : "r"(af[i][0]), "r"(af[i][1]), "r"(af[i][2]), "r"(af[i][3]),
                              "r"(bfr[jt][0]), "r"(bfr[jt][1]));
                    }
            }
        }

        // fragments -> gsm[n][b]
#pragma unroll
        for (int i = 0; i < 2; i++) {
            int m = wm * 32 + i * 16 + (lane >> 2);
#pragma unroll
            for (int jt = 0; jt < 2; jt++) {
                int n = wn * 16 + jt * 8 + (lane & 3) * 2;
                gsm[n * 132 + m]           = acc[i][jt][0];
                gsm[(n + 1) * 132 + m]     = acc[i][jt][1];
                gsm[n * 132 + m + 8]       = acc[i][jt][2];
                gsm[(n + 1) * 132 + m + 8] = acc[i][jt][3];
            }
        }
        __syncthreads();

        // epilogue: gates, activations, h/out stores
#pragma unroll
        for (int bi = 0; bi < 4; bi++) {
            int b = b0v + bi;
            float gi = gsm[(jl * 4 + 0) * 132 + b] + xr[bi][0];
            float gf = gsm[(jl * 4 + 1) * 132 + b] + xr[bi][1];
            float gg = gsm[(jl * 4 + 2) * 132 + b] + xr[bi][2];
            float go = gsm[(jl * 4 + 3) * 132 + b] + xr[bi][3];
            float ig = 1.f / (1.f + expf(-gi));
            float fg = 1.f / (1.f + expf(-gf));
            float og = 1.f / (1.f + expf(-go));
            float cc = fg * c4[bi] + ig * tanhf(gg);
            float hh = og * tanhf(cc);
            c4[bi] = cc;
            __nv_bfloat16 hb = __float2bfloat16(hh);
            hout[b * Hn + j] = hb;
            out[((size_t)t * Bn + b) * (2 * Hn) + dir * Hn + j] = hb;
        }

        // per-dir global barrier across the 64 blocks of this direction
        __syncthreads();
        if (tid == 0) {
            __threadfence();
            unsigned old = g_gen[dir];
            if (atomicAdd(&g_cnt[dir], 1u) == 63u) {
                g_cnt[dir] = 0;
                __threadfence();
                g_gen[dir] = old + 1u;
            } else {
                while (g_gen[dir] == old) { }
                __threadfence();
            }
        }
        __syncthreads();
    }
}

// ---------------- emissions: em[row][t] = hfc[row] . cls_w[t] + cls_b[t] ----------
__global__ void emissions_kernel(const float* __restrict__ hfc,
                                 const float* __restrict__ cls_w,
                                 const float* __restrict__ cls_b)
{
    int warp = blockIdx.x * 8 + (threadIdx.x >> 5);
    int lane = threadIdx.x & 31;
    const float* hrow = hfc + (size_t)warp * Hn;
    float hv[16];
#pragma unroll
    for (int q = 0; q < 16; q++) hv[q] = hrow[lane + q * 32];
    for (int tt = 0; tt < Tn; tt++) {
        const float* wr = cls_w + tt * Hn;
        float s = 0.f;
#pragma unroll
        for (int q = 0; q < 16; q++) s += hv[q] * wr[lane + q * 32];
#pragma unroll
        for (int o = 16; o > 0; o >>= 1) s += __shfl_xor_sync(0xffffffffu, s, o);
        if (lane == 0) d_em[(size_t)warp * Tn + tt] = s + cls_b[tt];
    }
}

// ---------------- CRF gold-path score (numerator), parallel over s ----------------
__global__ void crf_num_kernel(const int* __restrict__ ids, const int* __restrict__ tags,
                               const float* __restrict__ trans,
                               const float* __restrict__ start_t, const float* __restrict__ end_t)
{
    int b = blockIdx.x;
    int lane = threadIdx.x;   // 32
    float score = 0.f;
    int cnt = 0;
    for (int s = lane; s < Sn; s += 32) {
        int tg = tags[b * Sn + s];
        bool m = ids[b * Sn + s] != 0;
        if (s == 0) {
            score += start_t[tg] + d_em[(size_t)b * Tn + tg];
            if (m) cnt++;
        } else if (m) {
            int pv = tags[b * Sn + s - 1];
            score += trans[pv * Tn + tg] + d_em[((size_t)s * Bn + b) * Tn + tg];
            cnt++;
        }
    }
#pragma unroll
    for (int o = 16; o > 0; o >>= 1) {
        score += __shfl_xor_sync(0xffffffffu, score, o);
        cnt   += __shfl_xor_sync(0xffffffffu, cnt, o);
    }
    if (lane == 0) {
        int se = cnt - 1; if (se < 0) se = 0;
        d_num[b] = score + end_t[tags[b * Sn + se]];
    }
}

// ---------------- CRF forward algorithm (denominator) ----------------
__global__ void crf_fwd_kernel(const int* __restrict__ ids,
                               const float* __restrict__ trans,
                               const float* __restrict__ start_t,
                               const float* __restrict__ end_t)
{
    int b = blockIdx.x;
    int j = threadIdx.x;
    __shared__ float alpha[Tn];
    __shared__ float tr[Tn * Tn];
    for (int idx = j; idx < Tn * Tn; idx += 32) tr[idx] = trans[idx];
    if (j < Tn) alpha[j] = start_t[j] + d_em[(size_t)b * Tn + j];
    __syncthreads();
    for (int s = 1; s < Sn; s++) {
        bool m = ids[b * Sn + s] != 0;
        float ns = 0.f;
        if (m && j < Tn) {
            float mx = -1e30f;
#pragma unroll
            for (int i = 0; i < Tn; i++) mx = fmaxf(mx, alpha[i] + tr[i * Tn + j]);
            float sum = 0.f;
#pragma unroll
            for (int i = 0; i < Tn; i++) sum += expf(alpha[i] + tr[i * Tn + j] - mx);
            ns = mx + logf(sum) + d_em[((size_t)s * Bn + b) * Tn + j];
        }
        __syncthreads();
        if (m && j < Tn) alpha[j] = ns;
        __syncthreads();
    }
    if (j == 0) {
        float mx = -1e30f;
        for (int i = 0; i < Tn; i++) mx = fmaxf(mx, alpha[i] + end_t[i]);
        float sum = 0.f;
        for (int i = 0; i < Tn; i++) sum += expf(alpha[i] + end_t[i] - mx);
        d_den[b] = mx + logf(sum);
    }
}

// ---------------- final: out = mean(num - den) ----------------
__global__ void final_kernel(float* __restrict__ out)
{
    int tid = threadIdx.x;
    __shared__ float sm[128];
    sm[tid] = d_num[tid] - d_den[tid];
    __syncthreads();
    for (int o = 64; o > 0; o >>= 1) {
        if (tid < o) sm[tid] += sm[tid + o];
        __syncthreads();
    }
    if (tid == 0) out[0] = sm[0] / 128.f;
}

// ---------------- launch ----------------
extern "C" void kernel_launch(void* const* d_in, const int* in_sizes, int n_in,
                              void* d_out, int out_size)
{
    (void)in_sizes; (void)n_in; (void)out_size;
    const int*   ids      = (const int*)d_in[0];
    const int*   tags     = (const int*)d_in[1];
    const float* emb      = (const float*)d_in[2];
    const float* w_ih_l0f = (const float*)d_in[3];
    const float* w_hh_l0f = (const float*)d_in[4];
    const float* b_l0f    = (const float*)d_in[5];
    const float* w_ih_l0b = (const float*)d_in[6];
    const float* w_hh_l0b = (const float*)d_in[7];
    const float* b_l0b    = (const float*)d_in[8];
    const float* w_ih_l1f = (const float*)d_in[9];
    const float* w_hh_l1f = (const float*)d_in[10];
    const float* b_l1f    = (const float*)d_in[11];
    const float* w_ih_l1b = (const float*)d_in[12];
    const float* w_hh_l1b = (const float*)d_in[13];
    const float* b_l1b    = (const float*)d_in[14];
    const float* fc_w     = (const float*)d_in[15];
    const float* fc_b     = (const float*)d_in[16];
    const float* cls_w    = (const float*)d_in[17];
    const float* cls_b    = (const float*)d_in[18];
    const float* trans    = (const float*)d_in[19];
    const float* start_t  = (const float*)d_in[20];
    const float* end_t    = (const float*)d_in[21];
    float* out = (float*)d_out;

    float *pxf, *pxb, *phfc;
    __nv_bfloat16 *pxbuf, *pout0b, *pout1b, *pw0f, *pw0b, *pw1f, *pw1b, *pwfc, *phstb;
    cudaGetSymbolAddress((void**)&pxbuf, d_xb);
    cudaGetSymbolAddress((void**)&pxf,   d_xp_f);
    cudaGetSymbolAddress((void**)&pxb,   d_xp_b);
    cudaGetSymbolAddress((void**)&pout0b, d_out0b);
    cudaGetSymbolAddress((void**)&pout1b, d_out1b);
    cudaGetSymbolAddress((void**)&phfc,  d_hfc);
    cudaGetSymbolAddress((void**)&phstb, d_hstb);
    cudaGetSymbolAddress((void**)&pw0f,  d_wb_l0f);
    cudaGetSymbolAddress((void**)&pw0b,  d_wb_l0b);
    cudaGetSymbolAddress((void**)&pw1f,  d_wb_l1f);
    cudaGetSymbolAddress((void**)&pw1b,  d_wb_l1b);
    cudaGetSymbolAddress((void**)&pwfc,  d_wb_fc);

    const int SMEM_LSTM = 128 * 520 * 2 + 32 * 520 * 2 + 32 * 132 * 4;  // 183296 B
    cudaFuncSetAttribute(persist_lstm_tc, cudaFuncAttributeMaxDynamicSharedMemorySize, SMEM_LSTM);
    const int SMEM_GEMM = 2 * 128 * 72 * 2 * 2;  // 73728 B
    cudaFuncSetAttribute(gemm_bf16, cudaFuncAttributeMaxDynamicSharedMemorySize, SMEM_GEMM);

    // weight converts for the big GEMMs
    f2bf_kernel<<<(G4n * En / 4 + 255) / 256, 256>>>(w_ih_l0f, pw0f, G4n * En / 4);
    f2bf_kernel<<<(G4n * En / 4 + 255) / 256, 256>>>(w_ih_l0b, pw0b, G4n * En / 4);
    f2bf_kernel<<<(G4n * 2 * Hn / 4 + 255) / 256, 256>>>(w_ih_l1f, pw1f, G4n * 2 * Hn / 4);
    f2bf_kernel<<<(G4n * 2 * Hn / 4 + 255) / 256, 256>>>(w_ih_l1b, pw1b, G4n * 2 * Hn / 4);
    f2bf_kernel<<<(Hn * 2 * Hn / 4 + 255) / 256, 256>>>(fc_w, pwfc, Hn * 2 * Hn / 4);

    embed_kernel<<<Sn * Bn, 64>>>(ids, emb);

    // layer 0 input projections (row-major xp [t][b][g*512+j])
    dim3 g0(G4n / 128, (Sn * Bn) / 128);
    gemm_bf16<<<g0, 256, SMEM_GEMM>>>(pxbuf, pw0f, b_l0f, pxf, G4n, En, 0);
    gemm_bf16<<<g0, 256, SMEM_GEMM>>>(pxbuf, pw0b, b_l0b, pxb, G4n, En, 0);

    cudaMemsetAsync(phstb, 0, sizeof(d_hstb), 0);
    persist_lstm_tc<<<128, 256, SMEM_LSTM>>>(pxf, pxb, w_hh_l0f, w_hh_l0b, pout0b);

    // layer 1 input projections
    gemm_bf16<<<g0, 256, SMEM_GEMM>>>(pout0b, pw1f, b_l1f, pxf, G4n, 2 * Hn, 0);
    gemm_bf16<<<g0, 256, SMEM_GEMM>>>(pout0b, pw1b, b_l1b, pxb, G4n, 2 * Hn, 0);

    cudaMemsetAsync(phstb, 0, sizeof(d_hstb), 0);
    persist_lstm_tc<<<128, 256, SMEM_LSTM>>>(pxf, pxb, w_hh_l1f, w_hh_l1b, pout1b);

    // fc + relu (fp32 out for emissions)
    dim3 gfc(Hn / 128, (Sn * Bn) / 128);
    gemm_bf16<<<gfc, 256, SMEM_GEMM>>>(pout1b, pwfc, fc_b, phfc, Hn, 2 * Hn, 1);

    emissions_kernel<<<(Sn * Bn) / 8, 256>>>(phfc, cls_w, cls_b);
    crf_num_kernel<<<Bn, 32>>>(ids, tags, trans, start_t, end_t);
    crf_fwd_kernel<<<Bn, 32>>>(ids, trans, start_t, end_t);
    final_kernel<<<1, Bn>>>(out);
}

// round 15
// speedup vs baseline: 1.2014x; 1.1084x over previous
#include <cuda_runtime.h>
#include <cuda_bf16.h>
#include <math.h>

#define Sn 256
#define Bn 128
#define En 256
#define Hn 512
#define Tn 18
#define G4n 2048

// ---------------- scratch (device globals; no cudaMalloc allowed) ----------------
__device__ __nv_bfloat16 d_xb[Sn * Bn * En];          // embedded input, bf16
__device__ float d_xp_f[Sn * Bn * G4n];               // input projection fwd [t][b][g*512+j]
__device__ float d_xp_b[Sn * Bn * G4n];               // input projection bwd
__device__ __nv_bfloat16 d_out0b[Sn * Bn * 2 * Hn];   // layer0 output bf16 [t][b][2H]
__device__ __nv_bfloat16 d_out1b[Sn * Bn * 2 * Hn];   // layer1 output bf16
__device__ float d_hfc[Sn * Bn * Hn];
__device__ float d_em[Sn * Bn * Tn];
__device__ __nv_bfloat16 d_hstb[2][2][Bn * Hn];       // h state bf16 [dir][parity][b*H+j]
__device__ float d_num[Bn];
__device__ float d_den[Bn];
__device__ unsigned g_cnt[2];
__device__ volatile unsigned g_gen[2];
// bf16 weight copies (input projections + fc)
__device__ __nv_bfloat16 d_wb_l0f[G4n * En];
__device__ __nv_bfloat16 d_wb_l0b[G4n * En];
__device__ __nv_bfloat16 d_wb_l1f[G4n * 2 * Hn];
__device__ __nv_bfloat16 d_wb_l1b[G4n * 2 * Hn];
__device__ __nv_bfloat16 d_wb_fc[Hn * 2 * Hn];

template<int N> __device__ __forceinline__ void cpwait() {
    asm volatile("cp.async.wait_group %0;" :: "n"(N));
}
__device__ __forceinline__ void cpcommit() {
    asm volatile("cp.async.commit_group;");
}
__device__ __forceinline__ void cpasync16(unsigned dst, const void* src) {
    asm volatile("cp.async.cg.shared.global [%0], [%1], 16;" :: "r"(dst), "l"(src));
}

// ---------------- fp32 -> bf16 convert ----------------
__global__ void f2bf_kernel(const float* __restrict__ src, __nv_bfloat16* __restrict__ dst, int n4)
{
    int i = blockIdx.x * blockDim.x + threadIdx.x;
    if (i >= n4) return;
    float4 v = ((const float4*)src)[i];
    __nv_bfloat162 h0 = __floats2bfloat162_rn(v.x, v.y);
    __nv_bfloat162 h1 = __floats2bfloat162_rn(v.z, v.w);
    ((__nv_bfloat162*)dst)[i * 2]     = h0;
    ((__nv_bfloat162*)dst)[i * 2 + 1] = h1;
}

// ---------------- embedding lookup (padding_idx=0 -> zeros), bf16 out ----------------
__global__ void embed_kernel(const int* __restrict__ ids, const float* __restrict__ emb)
{
    int n = blockIdx.x;          // n = s*B + b
    int s = n >> 7;
    int b = n & 127;
    int id = ids[b * Sn + s];
    float4 v;
    if (id == 0) v = make_float4(0.f, 0.f, 0.f, 0.f);
    else         v = ((const float4*)(emb + (size_t)id * En))[threadIdx.x];
    __nv_bfloat162 h0 = __floats2bfloat162_rn(v.x, v.y);
    __nv_bfloat162 h1 = __floats2bfloat162_rn(v.z, v.w);
    __nv_bfloat162* dst = (__nv_bfloat162*)(d_xb + (size_t)n * En);
    dst[threadIdx.x * 2]     = h0;
    dst[threadIdx.x * 2 + 1] = h1;
}

// ---------------- bf16 TC GEMM (NT), 2-stage cp.async, warp tile 64x64 -----------
// C[M,N] = A[M,K]*W[N,K]^T + bias. BM=128, BN=128, BK=64, 128 thr (4 warps, 2x2).
// Per K=16 slice per warp: 4 A-ldmatrix.x4 + 4 B-ldmatrix.x4 -> 32 MMAs (1:4).
// Dynamic smem: 2 stages x (A,B) x 128 x 72 bf16 = 73728 B. K % 64 == 0.
__global__ __launch_bounds__(128) void gemm_bf16(
    const __nv_bfloat16* __restrict__ A, const __nv_bfloat16* __restrict__ W,
    const float* __restrict__ bias, float* __restrict__ C,
    int N, int K, int relu)
{
    extern __shared__ __nv_bfloat16 gsmem[];
    __nv_bfloat16* As = gsmem;                 // [2][128*72]
    __nv_bfloat16* Bs = gsmem + 2 * 128 * 72;  // [2][128*72]

    int tid = threadIdx.x;
    int lane = tid & 31, wid = tid >> 5;
    int wm = wid >> 1, wn = wid & 1;           // 2x2 warp grid, 64x64 per warp
    int m0 = blockIdx.y << 7, n0 = blockIdx.x << 7;

    unsigned as_u32 = (unsigned)__cvta_generic_to_shared(As);
    unsigned bs_u32 = (unsigned)__cvta_generic_to_shared(Bs);
    // A x4: lanes 0-15 -> rows 0-15 k-low; 16-31 -> rows 0-15 k-high
    unsigned a_base = as_u32 + ((wm * 64 + (lane & 15)) * 72 + ((lane >> 4) * 8)) * 2;
    // B x4: g=lane>>3: m0=(rows n..n+7,klow), m1=(khigh), m2=(rows n+8..n+15,klow), m3=(khigh)
    {
    }
    int bg = lane >> 3, br = lane & 7;
    unsigned b_base = bs_u32 + ((wn * 64 + (bg >> 1) * 8 + br) * 72 + (bg & 1) * 8) * 2;
    const unsigned STB = 128 * 72 * 2;   // stage stride bytes

    // per-thread load coords: 8 x 16B per matrix per stage (128 rows x 64 cols)
    int rr[8], cc[8];
#pragma unroll
    for (int i = 0; i < 8; i++) {
        int q = i * 128 + tid;
        rr[i] = q >> 3;
        cc[i] = (q & 7) * 8;
    }

    float acc[4][8][4];
#pragma unroll
    for (int i = 0; i < 4; i++)
#pragma unroll
        for (int j = 0; j < 8; j++)
#pragma unroll
            for (int r = 0; r < 4; r++) acc[i][j][r] = 0.f;

    // prologue: stage 0
#pragma unroll
    for (int i = 0; i < 8; i++) {
        cpasync16(as_u32 + (rr[i] * 72 + cc[i]) * 2, &A[(size_t)(m0 + rr[i]) * K + cc[i]]);
        cpasync16(bs_u32 + (rr[i] * 72 + cc[i]) * 2, &W[(size_t)(n0 + rr[i]) * K + cc[i]]);
    }
    cpcommit();

    int st = 0;
    for (int k0 = 0; k0 < K; k0 += 64) {
        bool more = (k0 + 64) < K;
        if (more) {
            unsigned so = (st ^ 1) * STB;
#pragma unroll
            for (int i = 0; i < 8; i++) {
                cpasync16(as_u32 + so + (rr[i] * 72 + cc[i]) * 2,
                          &A[(size_t)(m0 + rr[i]) * K + k0 + 64 + cc[i]]);
                cpasync16(bs_u32 + so + (rr[i] * 72 + cc[i]) * 2,
                          &W[(size_t)(n0 + rr[i]) * K + k0 + 64 + cc[i]]);
            }
            cpcommit();
            cpwait<1>();
        } else {
            cpwait<0>();
        }
        __syncthreads();

        unsigned so = st * STB;
#pragma unroll
        for (int kk = 0; kk < 4; kk++) {
            unsigned af[4][4], bf[8][2];
#pragma unroll
            for (int i = 0; i < 4; i++) {
                unsigned addr = a_base + so + i * (16 * 72 * 2) + kk * 32;
                asm volatile("ldmatrix.sync.aligned.m8n8.x4.shared.b16 {%0,%1,%2,%3}, [%4];"
                    : "=r"(af[i][0]), "=r"(af[i][1]), "=r"(af[i][2]), "=r"(af[i][3])
                    : "r"(addr));
            }
#pragma unroll
            for (int jj = 0; jj < 4; jj++) {
                unsigned addr = b_base + so + jj * (16 * 72 * 2) + kk * 32;
                asm volatile("ldmatrix.sync.aligned.m8n8.x4.shared.b16 {%0,%1,%2,%3}, [%4];"
                    : "=r"(bf[2 * jj][0]), "=r"(bf[2 * jj][1]),
                      "=r"(bf[2 * jj + 1][0]), "=r"(bf[2 * jj + 1][1])
                    : "r"(addr));
            }
#pragma unroll
            for (int i = 0; i < 4; i++)
#pragma unroll
                for (int j = 0; j < 8; j++) {
                    asm volatile(
                        "mma.sync.aligned.m16n8k16.row.col.f32.bf16.bf16.f32 "
                        "{%0,%1,%2,%3}, {%4,%5,%6,%7}, {%8,%9}, {%0,%1,%2,%3};"
                        : "+f"(acc[i][j][0]), "+f"(acc[i][j][1]),
                          "+f"(acc[i][j][2]), "+f"(acc[i][j][3])
                        : "r"(af[i][0]), "r"(af[i][1]), "r"(af[i][2]), "r"(af[i][3]),
                          "r"(bf[j][0]), "r"(bf[j][1]));
                }
        }
        __syncthreads();
        st ^= 1;
    }

#pragma unroll
    for (int i = 0; i < 4; i++) {
        int mb = m0 + wm * 64 + i * 16 + (lane >> 2);
#pragma unroll
        for (int j = 0; j < 8; j++) {
            int nb = n0 + wn * 64 + j * 8 + (lane & 3) * 2;
            float bx = bias[nb], by = bias[nb + 1];
            float2 v0 = make_float2(acc[i][j][0] + bx, acc[i][j][1] + by);
            float2 v1 = make_float2(acc[i][j][2] + bx, acc[i][j][3] + by);
            if (relu) {
                v0.x = fmaxf(v0.x, 0.f); v0.y = fmaxf(v0.y, 0.f);
                v1.x = fmaxf(v1.x, 0.f); v1.y = fmaxf(v1.y, 0.f);
            }
            *(float2*)&C[(size_t)mb * N + nb]       = v0;
            *(float2*)&C[(size_t)(mb + 8) * N + nb] = v1;
        }
    }
}

// ---------------- persistent BiLSTM layer, tensor-core recurrence (R7-proven) ----
__global__ __launch_bounds__(256) void persist_lstm_tc(
    const float* __restrict__ xpf, const float* __restrict__ xpb,
    const float* __restrict__ whhf, const float* __restrict__ whhb,
    __nv_bfloat16* __restrict__ out)
{
    extern __shared__ __nv_bfloat16 smb[];
    __nv_bfloat16* hs = smb;                       // [128][520] bf16 (133120 B)
    __nv_bfloat16* ws = smb + 128 * 520;           // [32][520]  bf16 (33280 B)
    float* gsm = (float*)(smb + 128 * 520 + 32 * 520);  // [32][132] f32 (16896 B)

    int bid = blockIdx.x;
    int dir = bid >> 6;
    int j0 = (bid & 63) * 8;
    const float* xp  = dir ? xpb : xpf;
    const float* whh = dir ? whhb : whhf;

    int tid = threadIdx.x;
    int lane = tid & 31, wid = tid >> 5;
    int wm = wid >> 1, wn = wid & 1;               // 4x2 warp grid
    int jl = tid & 7, bg = tid >> 3;
    int b0v = bg * 4;
    int j = j0 + jl;

#pragma unroll 4
    for (int it = 0; it < 64; it++) {
        int idx = it * 256 + tid;
        int n = idx >> 9, k = idx & 511;
        int grow = (n & 3) * Hn + j0 + (n >> 2);
        ws[n * 520 + k] = __float2bfloat16(whh[(size_t)grow * Hn + k]);
    }
    float c4[4] = {0.f, 0.f, 0.f, 0.f};
    __syncthreads();

    unsigned hs_u = (unsigned)__cvta_generic_to_shared(hs);
    unsigned ws_u = (unsigned)__cvta_generic_to_shared(ws);
    unsigned a_base = hs_u + ((wm * 32 + (lane & 15)) * 520 + (lane >> 4) * 8) * 2;
    unsigned b_base = ws_u + ((wn * 16 + (lane & 7)) * 520 + ((lane >> 3) & 1) * 8) * 2;

    for (int s = 0; s < Sn; s++) {
        int t = dir ? (Sn - 1 - s) : s;
        const __nv_bfloat16* hin = d_hstb[dir][s & 1];
        __nv_bfloat16* hout = d_hstb[dir][(s & 1) ^ 1];

#pragma unroll
        for (int ch = 0; ch < 8; ch++) {
#pragma unroll
            for (int it = 0; it < 4; it++) {
                int idx = it * 256 + tid;
                int b = idx >> 3;
                int cq = idx & 7;
                cpasync16(hs_u + (b * 520 + ch * 64 + cq * 8) * 2,
                          hin + (size_t)b * Hn + ch * 64 + cq * 8);
            }
            cpcommit();
        }

        float xr[4][4];
#pragma unroll
        for (int bi = 0; bi < 4; bi++) {
            size_t xb = ((size_t)t * Bn + b0v + bi) * G4n;
#pragma unroll
            for (int g = 0; g < 4; g++)
                xr[bi][g] = xp[xb + g * Hn + j];
        }

        float acc[2][2][4];
#pragma unroll
        for (int i = 0; i < 2; i++)
#pragma unroll
            for (int jt = 0; jt < 2; jt++)
#pragma unroll
                for (int r = 0; r < 4; r++) acc[i][jt][r] = 0.f;

#pragma unroll
        for (int ch = 0; ch < 8; ch++) {
            if      (ch == 0) cpwait<7>();
            else if (ch == 1) cpwait<6>();
            else if (ch == 2) cpwait<5>();
            else if (ch == 3) cpwait<4>();
            else if (ch == 4) cpwait<3>();
            else if (ch == 5) cpwait<2>();
            else if (ch == 6) cpwait<1>();
            else              cpwait<0>();
            __syncthreads();
#pragma unroll
            for (int k2 = 0; k2 < 4; k2++) {
                int k = ch * 4 + k2;
                unsigned af[2][4], bfr[2][2];
#pragma unroll
                for (int i = 0; i < 2; i++) {
                    unsigned addr = a_base + i * (16 * 520 * 2) + k * 32;
                    asm volatile("ldmatrix.sync.aligned.m8n8.x4.shared.b16 {%0,%1,%2,%3}, [%4];"
                        : "=r"(af[i][0]), "=r"(af[i][1]), "=r"(af[i][2]), "=r"(af[i][3])
                        : "r"(addr));
                }
#pragma unroll
                for (int jt = 0; jt < 2; jt++) {
                    unsigned addr = b_base + jt * (8 * 520 * 2) + k * 32;
                    asm volatile("ldmatrix.sync.aligned.m8n8.x2.shared.b16 {%0,%1}, [%2];"
                        : "=r"(bfr[jt][0]), "=r"(bfr[jt][1]) : "r"(addr));
                }
#pragma unroll
                for (int i = 0; i < 2; i++)
#pragma unroll
                    for (int jt = 0; jt < 2; jt++) {
                        asm volatile(
                            "mma.sync.aligned.m16n8k16.row.col.f32.bf16.bf16.f32 "
                            "{%0,%1,%2,%3}, {%4,%5,%6,%7}, {%8,%9}, {%0,%1,%2,%3};"
                            : "+f"(acc[i][jt][0]), "+f"(acc[i][jt][1]),
                              "+f"(acc[i][jt][2]), "+f"(acc[i][jt][3])
                            : "r"(af[i][0]), "r"(af[i][1]), "r"(af[i][2]), "r"(af[i][3]),
                              "r"(bfr[jt][0]), "r"(bfr[jt][1]));
                    }
            }
        }

#pragma unroll
        for (int i = 0; i < 2; i++) {
            int m = wm * 32 + i * 16 + (lane >> 2);
#pragma unroll
            for (int jt = 0; jt < 2; jt++) {
                int n = wn * 16 + jt * 8 + (lane & 3) * 2;
                gsm[n * 132 + m]           = acc[i][jt][0];
                gsm[(n + 1) * 132 + m]     = acc[i][jt][1];
                gsm[n * 132 + m + 8]       = acc[i][jt][2];
                gsm[(n + 1) * 132 + m + 8] = acc[i][jt][3];
            }
        }
        __syncthreads();

#pragma unroll
        for (int bi = 0; bi < 4; bi++) {
            int b = b0v + bi;
            float gi = gsm[(jl * 4 + 0) * 132 + b] + xr[bi][0];
            float gf = gsm[(jl * 4 + 1) * 132 + b] + xr[bi][1];
            float gg = gsm[(jl * 4 + 2) * 132 + b] + xr[bi][2];
            float go = gsm[(jl * 4 + 3) * 132 + b] + xr[bi][3];
            float ig = 1.f / (1.f + expf(-gi));
            float fg = 1.f / (1.f + expf(-gf));
            float og = 1.f / (1.f + expf(-go));
            float cc = fg * c4[bi] + ig * tanhf(gg);
            float hh = og * tanhf(cc);
            c4[bi] = cc;
            __nv_bfloat16 hb = __float2bfloat16(hh);
            hout[b * Hn + j] = hb;
            out[((size_t)t * Bn + b) * (2 * Hn) + dir * Hn + j] = hb;
        }

        __syncthreads();
        if (tid == 0) {
            __threadfence();
            unsigned old = g_gen[dir];
            if (atomicAdd(&g_cnt[dir], 1u) == 63u) {
                g_cnt[dir] = 0;
                __threadfence();
                g_gen[dir] = old + 1u;
            } else {
                while (g_gen[dir] == old) { }
                __threadfence();
            }
        }
        __syncthreads();
    }
}

// ---------------- emissions: em[row][t] = hfc[row] . cls_w[t] + cls_b[t] ----------
__global__ void emissions_kernel(const float* __restrict__ hfc,
                                 const float* __restrict__ cls_w,
                                 const float* __restrict__ cls_b)
{
    int warp = blockIdx.x * 8 + (threadIdx.x >> 5);
    int lane = threadIdx.x & 31;
    const float* hrow = hfc + (size_t)warp * Hn;
    float hv[16];
#pragma unroll
    for (int q = 0; q < 16; q++) hv[q] = hrow[lane + q * 32];
    for (int tt = 0; tt < Tn; tt++) {
        const float* wr = cls_w + tt * Hn;
        float s = 0.f;
#pragma unroll
        for (int q = 0; q < 16; q++) s += hv[q] * wr[lane + q * 32];
#pragma unroll
        for (int o = 16; o > 0; o >>= 1) s += __shfl_xor_sync(0xffffffffu, s, o);
        if (lane == 0) d_em[(size_t)warp * Tn + tt] = s + cls_b[tt];
    }
}

// ---------------- CRF gold-path score (numerator), parallel over s ----------------
__global__ void crf_num_kernel(const int* __restrict__ ids, const int* __restrict__ tags,
                               const float* __restrict__ trans,
                               const float* __restrict__ start_t, const float* __restrict__ end_t)
{
    int b = blockIdx.x;
    int lane = threadIdx.x;
    float score = 0.f;
    int cnt = 0;
    for (int s = lane; s < Sn; s += 32) {
        int tg = tags[b * Sn + s];
        bool m = ids[b * Sn + s] != 0;
        if (s == 0) {
            score += start_t[tg] + d_em[(size_t)b * Tn + tg];
            if (m) cnt++;
        } else if (m) {
            int pv = tags[b * Sn + s - 1];
            score += trans[pv * Tn + tg] + d_em[((size_t)s * Bn + b) * Tn + tg];
            cnt++;
        }
    }
#pragma unroll
    for (int o = 16; o > 0; o >>= 1) {
        score += __shfl_xor_sync(0xffffffffu, score, o);
        cnt   += __shfl_xor_sync(0xffffffffu, cnt, o);
    }
    if (lane == 0) {
        int se = cnt - 1; if (se < 0) se = 0;
        d_num[b] = score + end_t[tags[b * Sn + se]];
    }
}

// ---------------- CRF forward algorithm (denominator) ----------------
__global__ void crf_fwd_kernel(const int* __restrict__ ids,
                               const float* __restrict__ trans,
                               const float* __restrict__ start_t,
                               const float* __restrict__ end_t)
{
    int b = blockIdx.x;
    int j = threadIdx.x;
    __shared__ float alpha[Tn];
    __shared__ float tr[Tn * Tn];
    for (int idx = j; idx < Tn * Tn; idx += 32) tr[idx] = trans[idx];
    if (j < Tn) alpha[j] = start_t[j] + d_em[(size_t)b * Tn + j];
    __syncthreads();
    for (int s = 1; s < Sn; s++) {
        bool m = ids[b * Sn + s] != 0;
        float ns = 0.f;
        if (m && j < Tn) {
            float mx = -1e30f;
#pragma unroll
            for (int i = 0; i < Tn; i++) mx = fmaxf(mx, alpha[i] + tr[i * Tn + j]);
            float sum = 0.f;
#pragma unroll
            for (int i = 0; i < Tn; i++) sum += expf(alpha[i] + tr[i * Tn + j] - mx);
            ns = mx + logf(sum) + d_em[((size_t)s * Bn + b) * Tn + j];
        }
        __syncthreads();
        if (m && j < Tn) alpha[j] = ns;
        __syncthreads();
    }
    if (j == 0) {
        float mx = -1e30f;
        for (int i = 0; i < Tn; i++) mx = fmaxf(mx, alpha[i] + end_t[i]);
        float sum = 0.f;
        for (int i = 0; i < Tn; i++) sum += expf(alpha[i] + end_t[i] - mx);
        d_den[b] = mx + logf(sum);
    }
}

// ---------------- final: out = mean(num - den) ----------------
__global__ void final_kernel(float* __restrict__ out)
{
    int tid = threadIdx.x;
    __shared__ float sm[128];
    sm[tid] = d_num[tid] - d_den[tid];
    __syncthreads();
    for (int o = 64; o > 0; o >>= 1) {
        if (tid < o) sm[tid] += sm[tid + o];
        __syncthreads();
    }
    if (tid == 0) out[0] = sm[0] / 128.f;
}

// ---------------- launch ----------------
extern "C" void kernel_launch(void* const* d_in, const int* in_sizes, int n_in,
                              void* d_out, int out_size)
{
    (void)in_sizes; (void)n_in; (void)out_size;
    const int*   ids      = (const int*)d_in[0];
    const int*   tags     = (const int*)d_in[1];
    const float* emb      = (const float*)d_in[2];
    const float* w_ih_l0f = (const float*)d_in[3];
    const float* w_hh_l0f = (const float*)d_in[4];
    const float* b_l0f    = (const float*)d_in[5];
    const float* w_ih_l0b = (const float*)d_in[6];
    const float* w_hh_l0b = (const float*)d_in[7];
    const float* b_l0b    = (const float*)d_in[8];
    const float* w_ih_l1f = (const float*)d_in[9];
    const float* w_hh_l1f = (const float*)d_in[10];
    const float* b_l1f    = (const float*)d_in[11];
    const float* w_ih_l1b = (const float*)d_in[12];
    const float* w_hh_l1b = (const float*)d_in[13];
    const float* b_l1b    = (const float*)d_in[14];
    const float* fc_w     = (const float*)d_in[15];
    const float* fc_b     = (const float*)d_in[16];
    const float* cls_w    = (const float*)d_in[17];
    const float* cls_b    = (const float*)d_in[18];
    const float* trans    = (const float*)d_in[19];
    const float* start_t  = (const float*)d_in[20];
    const float* end_t    = (const float*)d_in[21];
    float* out = (float*)d_out;

    float *pxf, *pxb, *phfc;
    __nv_bfloat16 *pxbuf, *pout0b, *pout1b, *pw0f, *pw0b, *pw1f, *pw1b, *pwfc, *phstb;
    cudaGetSymbolAddress((void**)&pxbuf, d_xb);
    cudaGetSymbolAddress((void**)&pxf,   d_xp_f);
    cudaGetSymbolAddress((void**)&pxb,   d_xp_b);
    cudaGetSymbolAddress((void**)&pout0b, d_out0b);
    cudaGetSymbolAddress((void**)&pout1b, d_out1b);
    cudaGetSymbolAddress((void**)&phfc,  d_hfc);
    cudaGetSymbolAddress((void**)&phstb, d_hstb);
    cudaGetSymbolAddress((void**)&pw0f,  d_wb_l0f);
    cudaGetSymbolAddress((void**)&pw0b,  d_wb_l0b);
    cudaGetSymbolAddress((void**)&pw1f,  d_wb_l1f);
    cudaGetSymbolAddress((void**)&pw1b,  d_wb_l1b);
    cudaGetSymbolAddress((void**)&pwfc,  d_wb_fc);

    const int SMEM_LSTM = 128 * 520 * 2 + 32 * 520 * 2 + 32 * 132 * 4;  // 183296 B
    cudaFuncSetAttribute(persist_lstm_tc, cudaFuncAttributeMaxDynamicSharedMemorySize, SMEM_LSTM);
    const int SMEM_GEMM = 2 * 128 * 72 * 2 * 2;  // 73728 B
    cudaFuncSetAttribute(gemm_bf16, cudaFuncAttributeMaxDynamicSharedMemorySize, SMEM_GEMM);

    // weight converts for the big GEMMs
    f2bf_kernel<<<(G4n * En / 4 + 255) / 256, 256>>>(w_ih_l0f, pw0f, G4n * En / 4);
    f2bf_kernel<<<(G4n * En / 4 + 255) / 256, 256>>>(w_ih_l0b, pw0b, G4n * En / 4);
    f2bf_kernel<<<(G4n * 2 * Hn / 4 + 255) / 256, 256>>>(w_ih_l1f, pw1f, G4n * 2 * Hn / 4);
    f2bf_kernel<<<(G4n * 2 * Hn / 4 + 255) / 256, 256>>>(w_ih_l1b, pw1b, G4n * 2 * Hn / 4);
    f2bf_kernel<<<(Hn * 2 * Hn / 4 + 255) / 256, 256>>>(fc_w, pwfc, Hn * 2 * Hn / 4);

    embed_kernel<<<Sn * Bn, 64>>>(ids, emb);

    // layer 0 input projections (row-major xp [t][b][g*512+j])
    dim3 g0(G4n / 128, (Sn * Bn) / 128);
    gemm_bf16<<<g0, 128, SMEM_GEMM>>>(pxbuf, pw0f, b_l0f, pxf, G4n, En, 0);
    gemm_bf16<<<g0, 128, SMEM_GEMM>>>(pxbuf, pw0b, b_l0b, pxb, G4n, En, 0);

    cudaMemsetAsync(phstb, 0, sizeof(d_hstb), 0);
    persist_lstm_tc<<<128, 256, SMEM_LSTM>>>(pxf, pxb, w_hh_l0f, w_hh_l0b, pout0b);

    // layer 1 input projections
    gemm_bf16<<<g0, 128, SMEM_GEMM>>>(pout0b, pw1f, b_l1f, pxf, G4n, 2 * Hn, 0);
    gemm_bf16<<<g0, 128, SMEM_GEMM>>>(pout0b, pw1b, b_l1b, pxb, G4n, 2 * Hn, 0);

    cudaMemsetAsync(phstb, 0, sizeof(d_hstb), 0);
    persist_lstm_tc<<<128, 256, SMEM_LSTM>>>(pxf, pxb, w_hh_l1f, w_hh_l1b, pout1b);

    // fc + relu (fp32 out for emissions)
    dim3 gfc(Hn / 128, (Sn * Bn) / 128);
    gemm_bf16<<<gfc, 128, SMEM_GEMM>>>(pout1b, pwfc, fc_b, phfc, Hn, 2 * Hn, 1);

    emissions_kernel<<<(Sn * Bn) / 8, 256>>>(phfc, cls_w, cls_b);
    crf_num_kernel<<<Bn, 32>>>(ids, tags, trans, start_t, end_t);
    crf_fwd_kernel<<<Bn, 32>>>(ids, trans, start_t, end_t);
    final_kernel<<<1, Bn>>>(out);
}